// round 2
// baseline (speedup 1.0000x reference)
#include <cuda_runtime.h>
#include <math.h>
#include <float.h>

// Geometry
#define NROWS   131072
#define KCODE   512
#define BCH     262144          // 64*64*64 batch stride in z (B,C,H,W)

// d_out layout (fp32, outputs concatenated)
#define OFF_LOSS 0
#define OFF_ZQ   1
#define OFF_PERP 8388609
#define OFF_ENC  8388610ULL
#define OFF_CODE 75497474ULL    // OFF_ENC + NROWS*KCODE

__device__ int   g_codes[NROWS];
__device__ int   g_counts[KCODE];
__device__ float g_loss;

// ---- packed f32x2 fma helpers (per-lane IEEE fma.rn, identical to scalar) ----
__device__ __forceinline__ unsigned long long packbb(float x) {
    unsigned long long r;
    asm("mov.b64 %0, {%1,%1};" : "=l"(r) : "f"(x));
    return r;
}
// one LDS.128 feeding two sequential f32x2 fma steps (d, d+1) of two code-chains
__device__ __forceinline__ void step2(unsigned long long& acc,
                                      unsigned long long zb0,
                                      unsigned long long zb1,
                                      unsigned waddr) {
    unsigned long long w01, w23;
    asm("ld.shared.v2.u64 {%0,%1}, [%2];" : "=l"(w01), "=l"(w23) : "r"(waddr));
    asm("fma.rn.f32x2 %0, %1, %2, %0;" : "+l"(acc) : "l"(zb0), "l"(w01));
    asm("fma.rn.f32x2 %0, %1, %2, %0;" : "+l"(acc) : "l"(zb1), "l"(w23));
}
__device__ __forceinline__ void unpack2(unsigned long long a, float& lo, float& hi) {
    asm("mov.b64 {%0,%1}, %2;" : "=f"(lo), "=f"(hi) : "l"(a));
}

// ---------------------------------------------------------------------------
// init: reset accumulators
// ---------------------------------------------------------------------------
__global__ void vq_init() {
    int t = threadIdx.x;
    g_counts[t] = 0;
    if (t == 0) g_loss = 0.0f;
}

// ---------------------------------------------------------------------------
// main: per-thread row, emulate reference rounding pipeline exactly.
// d_k = fl( fl(zn + wn_k) - 2*dot_k ), strict < argmin (first index).
// zn  = strict-sequential  sum of fl(z_d^2)   (round-2 hypothesis)
// dot = ascending-d fma chain (Eigen gebp order)
// ---------------------------------------------------------------------------
__global__ __launch_bounds__(128, 1)
void vq_main(const float* __restrict__ z, const float* __restrict__ w,
             float* __restrict__ dout) {
    extern __shared__ float sm[];
    float* wp  = sm;                   // [32768] pair-interleaved: wp[p*128 + 2d + (k&1)]
    float* wn  = sm + 32768;           // [512]
    int*  hist = (int*)(sm + 33280);   // [512]
    float* red = sm + 33792;           // [4]

    const int tid = threadIdx.x;

    // stage weight pair-interleaved: pair p=(2p,2p+1), wp[p][d] = {w_2p[d], w_2p+1[d]}
    for (int idx = tid; idx < 32768; idx += 128) {
        int k = idx >> 6, d = idx & 63;
        wp[((k >> 1) << 7) + (d << 1) + (k & 1)] = w[idx];
    }
    for (int i = tid; i < 512; i += 128) hist[i] = 0;

    // wn_k: strict sequential adds of rounded squares
#pragma unroll
    for (int c = 0; c < 4; ++c) {
        int k = (tid << 2) + c;
        const float* wr = w + (k << 6);
        float s = __fmul_rn(wr[0], wr[0]);
        for (int d = 1; d < 64; ++d) s = __fadd_rn(s, __fmul_rn(wr[d], wr[d]));
        wn[k] = s;
    }
    __syncthreads();

    // this row of z
    const int n   = blockIdx.x * 128 + tid;
    const int b   = n >> 12;
    const int rem = n & 4095;
    const float* zp = z + (size_t)b * BCH + rem;
    float zz[64];
#pragma unroll
    for (int d = 0; d < 64; ++d) zz[d] = zp[(size_t)d << 12];

    // zn: strict sequential
    float zn = __fmul_rn(zz[0], zz[0]);
#pragma unroll
    for (int d = 1; d < 64; ++d) zn = __fadd_rn(zn, __fmul_rn(zz[d], zz[d]));

    const unsigned wbase = (unsigned)__cvta_generic_to_shared(wp);

    float best = FLT_MAX;
    int   bi   = 0;
    for (int p = 0; p < 256; p += 4) {      // 4 code-pairs in flight (8 chains)
        unsigned long long acc0 = 0, acc1 = 0, acc2 = 0, acc3 = 0;
        unsigned base = wbase + (unsigned)p * 512u;   // pair stride = 128 floats
#pragma unroll
        for (int i = 0; i < 32; ++i) {
            unsigned long long zb0 = packbb(zz[2 * i]);
            unsigned long long zb1 = packbb(zz[2 * i + 1]);
            unsigned a = base + (unsigned)(i << 4);
            step2(acc0, zb0, zb1, a);
            step2(acc1, zb0, zb1, a + 512u);
            step2(acc2, zb0, zb1, a + 1024u);
            step2(acc3, zb0, zb1, a + 1536u);
        }
        unsigned long long accs[4] = {acc0, acc1, acc2, acc3};
#pragma unroll
        for (int u = 0; u < 4; ++u) {
            float lo, hi;
            unpack2(accs[u], lo, hi);
            int k = (p + u) << 1;
            float d0 = __fsub_rn(__fadd_rn(zn, wn[k]),     __fadd_rn(lo, lo));
            float d1 = __fsub_rn(__fadd_rn(zn, wn[k + 1]), __fadd_rn(hi, hi));
            if (d0 < best) { best = d0; bi = k; }
            if (d1 < best) { best = d1; bi = k + 1; }
        }
    }

    // outputs for this row
    g_codes[n] = bi;
    dout[OFF_CODE + n] = (float)bi;
    atomicAdd(&hist[bi], 1);

    // z_q with straight-through rounding: fl(zp + fl(wq - zp)); loss accum
    const int pb = (bi >> 1) << 7, sel = bi & 1;
    float* zq = dout + OFF_ZQ + (size_t)b * BCH + rem;
    float ls = 0.0f;
#pragma unroll
    for (int d = 0; d < 64; ++d) {
        float wv   = wp[pb + (d << 1) + sel];
        float diff = __fsub_rn(wv, zz[d]);
        ls = fmaf(diff, diff, ls);
        zq[(size_t)d << 12] = __fadd_rn(zz[d], diff);
    }

    // block loss reduction (4 warps)
    const int lane = tid & 31, wid = tid >> 5;
#pragma unroll
    for (int off = 16; off > 0; off >>= 1)
        ls += __shfl_down_sync(0xFFFFFFFFu, ls, off);
    if (lane == 0) red[wid] = ls;
    __syncthreads();   // also orders hist atomics
    if (tid == 0)
        atomicAdd(&g_loss, ((red[0] + red[1]) + (red[2] + red[3])));
#pragma unroll
    for (int c = 0; c < 4; ++c)
        atomicAdd(&g_counts[(tid << 2) + c], hist[(tid << 2) + c]);
}

// ---------------------------------------------------------------------------
// encodings: one warp per row, write zeros + single 1.0 (float2 stores).
// ---------------------------------------------------------------------------
__global__ void vq_enc(float* __restrict__ dout) {
    const int row  = (blockIdx.x << 3) + (threadIdx.x >> 5);
    const int lane = threadIdx.x & 31;
    const int c    = g_codes[row];
    const int ci   = c >> 1;
    float2* out = (float2*)(dout + OFF_ENC) + (size_t)row * 256;
#pragma unroll
    for (int j = 0; j < 8; ++j) {
        int idx = (j << 5) + lane;
        float2 v = make_float2(0.0f, 0.0f);
        if (idx == ci) { if (c & 1) v.y = 1.0f; else v.x = 1.0f; }
        out[idx] = v;
    }
}

// ---------------------------------------------------------------------------
// finalize: loss and perplexity
// ---------------------------------------------------------------------------
__global__ void vq_final(float* __restrict__ dout) {
    __shared__ float sred[16];
    int t = threadIdx.x;  // 512
    float em = (float)g_counts[t] * (1.0f / 131072.0f);   // /2^17 exact
    float v  = em * logf(__fadd_rn(em, 1e-10f));
    int lane = t & 31, wid = t >> 5;
#pragma unroll
    for (int off = 16; off > 0; off >>= 1)
        v += __shfl_down_sync(0xFFFFFFFFu, v, off);
    if (lane == 0) sred[wid] = v;
    __syncthreads();
    if (wid == 0) {
        float s = (lane < 16) ? sred[lane] : 0.0f;
#pragma unroll
        for (int off = 8; off > 0; off >>= 1)
            s += __shfl_down_sync(0xFFFFFFFFu, s, off);
        if (lane == 0) {
            dout[OFF_PERP] = expf(-s);
            float m = g_loss * (1.0f / 8388608.0f);       // /2^23 exact
            dout[OFF_LOSS] = __fadd_rn(m, __fmul_rn(0.25f, m));
        }
    }
}

extern "C" void kernel_launch(void* const* d_in, const int* in_sizes, int n_in,
                              void* d_out, int out_size) {
    const float* z = (const float*)d_in[0];
    const float* w = (const float*)d_in[1];
    float* out = (float*)d_out;

    const int smem_bytes = 33796 * 4;
    cudaFuncSetAttribute(vq_main, cudaFuncAttributeMaxDynamicSharedMemorySize,
                         smem_bytes);

    vq_init<<<1, 512>>>();
    vq_main<<<1024, 128, smem_bytes>>>(z, w, out);
    vq_enc<<<16384, 256>>>(out);
    vq_final<<<1, 512>>>(out);
}

// round 4
// speedup vs baseline: 1.8351x; 1.8351x over previous
#include <cuda_runtime.h>
#include <math.h>
#include <float.h>

// Geometry
#define NROWS   131072
#define KCODE   512
#define BCH     262144           // 64*64*64 batch stride in z (B,C,H,W)
#define NTILES  2048             // NROWS / 64
#define GRID    148

// d_out layout (fp32, outputs concatenated)
#define OFF_LOSS 0
#define OFF_ZQ   1
#define OFF_PERP 8388609
#define OFF_ENC  8388610ULL
#define OFF_CODE 75497474ULL

// smem layout (float offsets)
#define S_ZT   0        // [4096]  z tile: zt[(p*64+r)*2 + (d&1)], p=d>>1
#define S_WP   4096     // [32768] weight: wp[d*512 + c]  (pair-major for f2 loads)
#define S_WN   36864    // [512]
#define S_ZN   37376    // [64]
#define S_PART 37440    // [256f]  = 128 u64 argmin partials
#define S_CODE 37696    // [64]    int rowcode
#define S_HIST 37760    // [512]   int
#define S_LRED 38272    // [16]
#define S_TOT  38288    // floats

__device__ int   g_counts[KCODE];
__device__ float g_loss;

__device__ __forceinline__ unsigned long long packbb(float x) {
    unsigned long long r;
    asm("mov.b64 %0, {%1,%1};" : "=l"(r) : "f"(x));
    return r;
}
__device__ __forceinline__ void unpack2(unsigned long long a, float& lo, float& hi) {
    asm("mov.b64 {%0,%1}, %2;" : "=f"(lo), "=f"(hi) : "l"(a));
}
__device__ __forceinline__ void lds128(unsigned long long& a, unsigned long long& b,
                                       unsigned addr) {
    asm("ld.shared.v2.u64 {%0,%1}, [%2];" : "=l"(a), "=l"(b) : "r"(addr));
}
__device__ __forceinline__ unsigned long long lds64(unsigned addr) {
    unsigned long long v;
    asm("ld.shared.u64 %0, [%1];" : "=l"(v) : "r"(addr));
    return v;
}
__device__ __forceinline__ void ffma2(unsigned long long& acc,
                                      unsigned long long a, unsigned long long b) {
    asm("fma.rn.f32x2 %0, %1, %2, %0;" : "+l"(acc) : "l"(a), "l"(b));
}
__device__ __forceinline__ unsigned orderable(float s) {
    unsigned ub = __float_as_uint(s);
    return (ub & 0x80000000u) ? ~ub : (ub | 0x80000000u);
}

__global__ void vq_init() {
    g_counts[threadIdx.x] = 0;
    if (threadIdx.x == 0) g_loss = 0.0f;
}

__global__ __launch_bounds__(512, 1)
void vq_gemm(const float* __restrict__ z, const float* __restrict__ w,
             float* __restrict__ dout) {
    extern __shared__ float sm[];
    float*              zt   = sm + S_ZT;
    float*              wp   = sm + S_WP;
    float*              wn   = sm + S_WN;
    float*              zn   = sm + S_ZN;
    unsigned long long* part = (unsigned long long*)(sm + S_PART);
    int*                rcd  = (int*)(sm + S_CODE);
    int*                hist = (int*)(sm + S_HIST);
    float*              lred = sm + S_LRED;

    const int tid = threadIdx.x;
    const int n   = tid & 63;          // n-thread (codes)
    const int mth = tid >> 6;          // m-thread (rows), 0..7

    // stage weight: wp[d*512 + c] = w[c*64 + d]  == pair layout [d][cp]{even,odd}
    for (int idx = tid; idx < 32768; idx += 512) {
        int c = idx >> 6, d = idx & 63;
        wp[d * 512 + c] = w[idx];
    }
    for (int i = tid; i < 512; i += 512) hist[i] = 0;
    __syncthreads();

    // wn[c]: strict sequential sum of rounded squares (reference order)
    {
        int c = tid;
        float v = wp[c];                       // d=0
        float s = __fmul_rn(v, v);
#pragma unroll
        for (int d = 1; d < 64; ++d) {
            v = wp[d * 512 + c];
            s = __fadd_rn(s, __fmul_rn(v, v));
        }
        wn[c] = s;
    }

    const unsigned smbase = (unsigned)__cvta_generic_to_shared(sm);
    const unsigned zbA    = smbase + S_ZT * 4 + mth * 64;   // rows mth*8.. (f2 bytes)
    const unsigned wbB    = smbase + S_WP * 4 + n * 8;      // code-pairs n+64j

    float ls = 0.0f;

    for (int tile = blockIdx.x; tile < NTILES; tile += GRID) {
        __syncthreads();   // zt/rcd reuse barrier
        const int    n0  = tile * 64;
        const int    b   = n0 >> 12;
        const int    rem = n0 & 4095;
        const float* zg  = z + (size_t)b * BCH + rem;

        // stage z tile (64 rows x 64 dims), pair layout
#pragma unroll
        for (int pass = 0; pass < 8; ++pass) {
            int d = pass * 8 + (tid >> 6);
            int r = tid & 63;
            zt[((d >> 1) * 64 + r) * 2 + (d & 1)] = zg[(size_t)d << 12] + 0.0f * r,
            zt[((d >> 1) * 64 + r) * 2 + (d & 1)] = zg[((size_t)d << 12) + r];
        }
        __syncthreads();

        // zn[r]: strict sequential (reference order)
        if (tid < 64) {
            int r = tid;
            float v = zt[r * 2];               // d=0
            float s = __fmul_rn(v, v);
#pragma unroll
            for (int d = 1; d < 64; ++d) {
                v = zt[((d >> 1) * 64 + r) * 2 + (d & 1)];
                s = __fadd_rn(s, __fmul_rn(v, v));
            }
            zn[r] = s;
        }

        // ---- k-loop: acc[i][j] lanes = codes (2cp, 2cp+1), sequential over d ----
        unsigned long long acc[32];
#pragma unroll
        for (int q = 0; q < 32; ++q) acc[q] = 0ULL;

#pragma unroll 4
        for (int p = 0; p < 32; ++p) {
            unsigned long long za[8];
#pragma unroll
            for (int q = 0; q < 4; ++q)
                lds128(za[2 * q], za[2 * q + 1], zbA + (unsigned)p * 512u + q * 16u);
            unsigned long long wb0[4], wb1[4];
#pragma unroll
            for (int j = 0; j < 4; ++j) {
                unsigned a = wbB + (unsigned)p * 4096u + (unsigned)j * 512u;
                wb0[j] = lds64(a);
                wb1[j] = lds64(a + 2048u);
            }
#pragma unroll
            for (int i = 0; i < 8; ++i) {
                float lo, hi;
                unpack2(za[i], lo, hi);
                unsigned long long dl = packbb(lo);
                unsigned long long dh = packbb(hi);
#pragma unroll
                for (int j = 0; j < 4; ++j) {
                    ffma2(acc[i * 4 + j], dl, wb0[j]);   // dim 2p
                    ffma2(acc[i * 4 + j], dh, wb1[j]);   // dim 2p+1
                }
            }
        }
        __syncthreads();   // zn ready; part/rcd free

        // ---- epilogue: exact score pipeline + argmin ----
#pragma unroll
        for (int i = 0; i < 8; ++i) {
            int   r   = mth * 8 + i;
            float znr = zn[r];
            unsigned long long key = 0xFFFFFFFFFFFFFFFFULL;
#pragma unroll
            for (int j = 0; j < 4; ++j) {
                float lo, hi;
                unpack2(acc[i * 4 + j], lo, hi);
                int c0 = 2 * (n + 64 * j);
                float s0 = __fsub_rn(__fadd_rn(znr, wn[c0]),     __fadd_rn(lo, lo));
                float s1 = __fsub_rn(__fadd_rn(znr, wn[c0 + 1]), __fadd_rn(hi, hi));
                unsigned long long k0 = ((unsigned long long)orderable(s0) << 32) | (unsigned)c0;
                unsigned long long k1 = ((unsigned long long)orderable(s1) << 32) | (unsigned)(c0 + 1);
                if (k0 < key) key = k0;
                if (k1 < key) key = k1;
            }
#pragma unroll
            for (int off = 16; off > 0; off >>= 1) {
                unsigned long long o = __shfl_down_sync(0xFFFFFFFFu, key, off);
                if (o < key) key = o;
            }
            if ((tid & 31) == 0) part[r * 2 + ((tid >> 5) & 1)] = key;
        }
        __syncthreads();

        if (tid < 64) {
            unsigned long long k0 = part[tid * 2], k1 = part[tid * 2 + 1];
            if (k1 < k0) k0 = k1;
            int code = (int)(unsigned)(k0 & 0xFFFFFFFFULL);
            rcd[tid] = code;
            dout[OFF_CODE + (size_t)(n0 + tid)] = (float)code;
            atomicAdd(&hist[code], 1);
        }
        __syncthreads();

        // ---- zq + loss (coalesced by dim) ----
        float* zqg = dout + OFF_ZQ + (size_t)b * BCH + rem;
#pragma unroll
        for (int pass = 0; pass < 8; ++pass) {
            int d = pass * 8 + (tid >> 6);
            int r = tid & 63;
            int code = rcd[r];
            float zv = zt[((d >> 1) * 64 + r) * 2 + (d & 1)];
            float wv = wp[d * 512 + code];
            float df = __fsub_rn(wv, zv);
            ls = fmaf(df, df, ls);
            zqg[((size_t)d << 12) + r] = __fadd_rn(zv, df);
        }

        // ---- encodings one-hot (268 MB total; overlaps next tile's FMAs) ----
        float2* encp = (float2*)(dout + OFF_ENC);
#pragma unroll
        for (int pass = 0; pass < 32; ++pass) {
            int e  = pass * 512 + tid;
            int r  = e >> 8;
            int c2 = e & 255;
            int code = rcd[r];
            float2 v = make_float2(0.0f, 0.0f);
            if (c2 == (code >> 1)) { if (code & 1) v.y = 1.0f; else v.x = 1.0f; }
            encp[(size_t)(n0 + r) * 256 + c2] = v;
        }
    }

    // flush loss + histogram
    __syncthreads();
    const int lane = tid & 31, wid = tid >> 5;
#pragma unroll
    for (int off = 16; off > 0; off >>= 1)
        ls += __shfl_down_sync(0xFFFFFFFFu, ls, off);
    if (lane == 0) lred[wid] = ls;
    __syncthreads();
    if (tid == 0) {
        float t = 0.0f;
#pragma unroll
        for (int i = 0; i < 16; ++i) t += lred[i];
        atomicAdd(&g_loss, t);
    }
    atomicAdd(&g_counts[tid], hist[tid]);
}

__global__ void vq_final(float* __restrict__ dout) {
    __shared__ float sred[16];
    int t = threadIdx.x;  // 512
    float em = (float)g_counts[t] * (1.0f / 131072.0f);
    float v  = em * logf(__fadd_rn(em, 1e-10f));
    int lane = t & 31, wid = t >> 5;
#pragma unroll
    for (int off = 16; off > 0; off >>= 1)
        v += __shfl_down_sync(0xFFFFFFFFu, v, off);
    if (lane == 0) sred[wid] = v;
    __syncthreads();
    if (wid == 0) {
        float s = (lane < 16) ? sred[lane] : 0.0f;
#pragma unroll
        for (int off = 8; off > 0; off >>= 1)
            s += __shfl_down_sync(0xFFFFFFFFu, s, off);
        if (lane == 0) {
            dout[OFF_PERP] = expf(-s);
            float m = g_loss * (1.0f / 8388608.0f);
            dout[OFF_LOSS] = __fadd_rn(m, __fmul_rn(0.25f, m));
        }
    }
}

extern "C" void kernel_launch(void* const* d_in, const int* in_sizes, int n_in,
                              void* d_out, int out_size) {
    const float* z = (const float*)d_in[0];
    const float* w = (const float*)d_in[1];
    float* out = (float*)d_out;

    const int smem_bytes = S_TOT * 4;
    cudaFuncSetAttribute(vq_gemm, cudaFuncAttributeMaxDynamicSharedMemorySize,
                         smem_bytes);

    vq_init<<<1, 512>>>();
    vq_gemm<<<GRID, 512, smem_bytes>>>(z, w, out);
    vq_final<<<1, 512>>>(out);
}